// round 9
// baseline (speedup 1.0000x reference)
#include <cuda_runtime.h>
#include <cstdint>

// N = M = 8192 points, 4 components. Single fused kernel, one graph node.
// Grid: 8 adv-blocks x 74 splits = 592 CTAs = 4 CTAs/SM on 148 SMs.
#define SPLITS 74
#define CHUNK 112            // per-split ori points (jn = 112 or 16 -> always even)
#define ADV_PER_BLOCK 1024
#define THREADS 256
#define T 4                  // adv points per thread
#define NMAX 8192
#define GRID_CTAS (8 * SPLITS)   // 592

// Per-point order-inverted min keys. key = 0x7FFFFFFF - float_bits(v), v >= 0.
// atomicMax(key) == atomicMin(v). Identity = 0 == zero-init state == what the
// last CTA resets to after consuming -> deterministic across graph replays.
__device__ unsigned int g_minkey[NMAX];
__device__ unsigned int g_tick;   // zero at load; atomicInc wraps back to 0 each replay

// Struct-of-pairs ori layout: one LDS.128 -> two packed f32x2 operands.
struct __align__(16) OriPair {
    float f[12];  // bx0 bx1 | by0 by1 | bz0 bz1 | bw0 bw1 | c0 c1 | pad pad
};

__device__ __forceinline__ uint64_t ffma2(uint64_t a, uint64_t b, uint64_t c) {
    uint64_t d;
    asm("fma.rn.f32x2 %0, %1, %2, %3;" : "=l"(d) : "l"(a), "l"(b), "l"(c));
    return d;
}
__device__ __forceinline__ uint64_t pack2(float x) {
    uint64_t d;
    asm("mov.b64 %0, {%1, %1};" : "=l"(d) : "f"(x));
    return d;
}
__device__ __forceinline__ float2 unpack2(uint64_t v) {
    float2 r;
    asm("mov.b64 {%0, %1}, %2;" : "=f"(r.x), "=f"(r.y) : "l"(v));
    return r;
}

__global__ __launch_bounds__(THREADS)
void hd_fused(const float* __restrict__ adv, const float* __restrict__ ori,
              float* __restrict__ out, int n, int m) {
    __shared__ OriPair sp[(CHUNK + 1) / 2];
    __shared__ int s_last;

    const int tid = threadIdx.x;
    const int j0  = blockIdx.y * CHUNK;
    const int jn  = min(CHUNK, m - j0);

    // ---- Stage ori chunk into pair layout ----
    for (int j = tid; j < jn; j += THREADS) {
        float4 b = reinterpret_cast<const float4*>(ori)[j0 + j];
        b.w *= 0.5f;  // INTENSITY_WEIGHT
        float c = b.x * b.x + b.y * b.y + b.z * b.z + b.w * b.w;
        float* dst = sp[j >> 1].f + (j & 1);
        dst[0] = b.x; dst[2] = b.y; dst[4] = b.z; dst[6] = b.w; dst[8] = c;
    }
    __syncthreads();

    uint64_t ax[T], ay[T], az[T], aw[T];
    float a2[T], mn[T];
    const int base = blockIdx.x * ADV_PER_BLOCK + tid;
#pragma unroll
    for (int k = 0; k < T; k++) {
        float4 a = reinterpret_cast<const float4*>(adv)[base + k * THREADS];
        a.w *= 0.5f;
        a2[k] = a.x * a.x + a.y * a.y + a.z * a.z + a.w * a.w;
        ax[k] = pack2(-2.0f * a.x);
        ay[k] = pack2(-2.0f * a.y);
        az[k] = pack2(-2.0f * a.z);
        aw[k] = pack2(-2.0f * a.w);
        mn[k] = INFINITY;
    }

    // ---- Mainloop (R4 form, rt-floor bound): 4 FFMA2 + 2 FMNMX per pair/k ----
    const int np = jn >> 1;   // 56 or 8 -> divisible by 4
#pragma unroll 4
    for (int p = 0; p < np; p++) {
        const ulonglong2 q0 = *reinterpret_cast<const ulonglong2*>(&sp[p].f[0]);
        const ulonglong2 q1 = *reinterpret_cast<const ulonglong2*>(&sp[p].f[4]);
        const uint64_t   cc = *reinterpret_cast<const uint64_t*>(&sp[p].f[8]);
#pragma unroll
        for (int k = 0; k < T; k++) {
            uint64_t d = ffma2(ax[k], q0.x, cc);
            d = ffma2(ay[k], q0.y, d);
            d = ffma2(az[k], q1.x, d);
            d = ffma2(aw[k], q1.y, d);
            float2 t = unpack2(d);
            mn[k] = fminf(mn[k], fminf(t.x, t.y));
        }
    }
    if (jn & 1) {   // never taken for these shapes, kept for safety
        const float* f = sp[(jn - 1) >> 1].f;
        const float bxx = f[0], byy = f[2], bzz = f[4], bww = f[6], c = f[8];
#pragma unroll
        for (int k = 0; k < T; k++) {
            float t = fmaf(unpack2(ax[k]).x, bxx, c);
            t = fmaf(unpack2(ay[k]).x, byy, t);
            t = fmaf(unpack2(az[k]).x, bzz, t);
            t = fmaf(unpack2(aw[k]).x, bww, t);
            mn[k] = fminf(mn[k], t);
        }
    }

    // ---- Epilogue: clamp >=0, invert, fire-and-forget REDG.MAX ----
#pragma unroll
    for (int k = 0; k < T; k++) {
        float v = fmaxf(mn[k] + a2[k], 0.0f);
        unsigned int key = 0x7FFFFFFFu - __float_as_uint(v);
        atomicMax(&g_minkey[base + k * THREADS], key);
    }

    // ---- Ticket: last CTA of the whole grid finishes the reduction ----
    __threadfence();          // make this thread's REDGs visible device-wide
    __syncthreads();          // all threads of this CTA fenced
    if (tid == 0) {
        unsigned old = atomicInc(&g_tick, GRID_CTAS - 1);  // wraps to 0 -> replay-safe
        s_last = (old == GRID_CTAS - 1);
    }
    __syncthreads();
    if (!s_last) return;

    // ---- Last CTA: consume 8192 keys (L2-resident), reset to identity 0 ----
    __threadfence();          // acquire side
    __shared__ float red[THREADS];
    float v = 0.0f;           // decoded values are >= 0
    const int nq = n / 4;     // 2048 uint4
#pragma unroll
    for (int q = tid; q < nq; q += THREADS) {   // 8 independent uint4 loads
        uint4 s = reinterpret_cast<uint4*>(g_minkey)[q];
        reinterpret_cast<uint4*>(g_minkey)[q] = make_uint4(0u, 0u, 0u, 0u);
        v = fmaxf(v, __uint_as_float(0x7FFFFFFFu - s.x));
        v = fmaxf(v, __uint_as_float(0x7FFFFFFFu - s.y));
        v = fmaxf(v, __uint_as_float(0x7FFFFFFFu - s.z));
        v = fmaxf(v, __uint_as_float(0x7FFFFFFFu - s.w));
    }
    red[tid] = v;
    __syncthreads();
    for (int off = THREADS / 2; off >= 32; off >>= 1) {
        if (tid < off) red[tid] = fmaxf(red[tid], red[tid + off]);
        __syncthreads();
    }
    if (tid < 32) {
        float w = red[tid];
#pragma unroll
        for (int off = 16; off > 0; off >>= 1)
            w = fmaxf(w, __shfl_xor_sync(0xffffffffu, w, off));
        if (tid == 0) out[0] = w;   // LOSS_WEIGHT = 1.0
    }
}

extern "C" void kernel_launch(void* const* d_in, const int* in_sizes, int n_in,
                              void* d_out, int out_size) {
    const float* adv = (const float*)d_in[0];
    const float* ori = (const float*)d_in[1];
    float* out = (float*)d_out;

    const int n = in_sizes[0] / 4;   // 8192
    const int m = in_sizes[1] / 4;   // 8192

    dim3 grid((n + ADV_PER_BLOCK - 1) / ADV_PER_BLOCK, SPLITS);
    hd_fused<<<grid, THREADS>>>(adv, ori, out, n, m);
}

// round 10
// speedup vs baseline: 1.0845x; 1.0845x over previous
#include <cuda_runtime.h>
#include <cstdint>

// N = M = 8192 points, 4 components. Single fused kernel, one graph node.
// Grid: 8 adv-blocks x 74 splits = 592 CTAs = 4 CTAs/SM on 148 SMs.
#define SPLITS 74
#define CHUNK 112            // per-split ori points (jn = 112 or 16 -> always even)
#define ADV_PER_BLOCK 1024
#define THREADS 256
#define T 4                  // adv points per thread
#define NMAX 8192
#define GRID_CTAS (8 * SPLITS)   // 592

// Per-point order-inverted min keys. key = 0x7FFFFFFF - float_bits(v), v >= 0.
// atomicMax(key) == atomicMin(v). Identity = 0 == zero-init state == what the
// last CTA resets to after consuming -> deterministic across graph replays.
__device__ unsigned int g_minkey[NMAX];
__device__ unsigned int g_tick;   // zero at load; inc wraps back to 0 each replay

// Struct-of-pairs ori layout: one LDS.128 -> two packed f32x2 operands.
struct __align__(16) OriPair {
    float f[12];  // bx0 bx1 | by0 by1 | bz0 bz1 | bw0 bw1 | c0 c1 | pad pad
};

__device__ __forceinline__ uint64_t ffma2(uint64_t a, uint64_t b, uint64_t c) {
    uint64_t d;
    asm("fma.rn.f32x2 %0, %1, %2, %3;" : "=l"(d) : "l"(a), "l"(b), "l"(c));
    return d;
}
__device__ __forceinline__ uint64_t pack2(float x) {
    uint64_t d;
    asm("mov.b64 %0, {%1, %1};" : "=l"(d) : "f"(x));
    return d;
}
__device__ __forceinline__ float2 unpack2(uint64_t v) {
    float2 r;
    asm("mov.b64 {%0, %1}, %2;" : "=f"(r.x), "=f"(r.y) : "l"(v));
    return r;
}

__global__ __launch_bounds__(THREADS)
void hd_fused(const float* __restrict__ adv, const float* __restrict__ ori,
              float* __restrict__ out, int n, int m) {
    __shared__ OriPair sp[(CHUNK + 1) / 2];
    __shared__ int s_last;

    const int tid = threadIdx.x;
    const int j0  = blockIdx.y * CHUNK;
    const int jn  = min(CHUNK, m - j0);

    // ---- Stage ori chunk into pair layout ----
    for (int j = tid; j < jn; j += THREADS) {
        float4 b = reinterpret_cast<const float4*>(ori)[j0 + j];
        b.w *= 0.5f;  // INTENSITY_WEIGHT
        float c = b.x * b.x + b.y * b.y + b.z * b.z + b.w * b.w;
        float* dst = sp[j >> 1].f + (j & 1);
        dst[0] = b.x; dst[2] = b.y; dst[4] = b.z; dst[6] = b.w; dst[8] = c;
    }
    __syncthreads();

    uint64_t ax[T], ay[T], az[T], aw[T];
    float a2[T], mn[T];
    const int base = blockIdx.x * ADV_PER_BLOCK + tid;
#pragma unroll
    for (int k = 0; k < T; k++) {
        float4 a = reinterpret_cast<const float4*>(adv)[base + k * THREADS];
        a.w *= 0.5f;
        a2[k] = a.x * a.x + a.y * a.y + a.z * a.z + a.w * a.w;
        ax[k] = pack2(-2.0f * a.x);
        ay[k] = pack2(-2.0f * a.y);
        az[k] = pack2(-2.0f * a.z);
        aw[k] = pack2(-2.0f * a.w);
        mn[k] = INFINITY;
    }

    // ---- Mainloop (rt-floor bound): 4 FFMA2 + 2 FMNMX per pair per k ----
    const int np = jn >> 1;   // 56 or 8 -> divisible by 4
#pragma unroll 4
    for (int p = 0; p < np; p++) {
        const ulonglong2 q0 = *reinterpret_cast<const ulonglong2*>(&sp[p].f[0]);
        const ulonglong2 q1 = *reinterpret_cast<const ulonglong2*>(&sp[p].f[4]);
        const uint64_t   cc = *reinterpret_cast<const uint64_t*>(&sp[p].f[8]);
#pragma unroll
        for (int k = 0; k < T; k++) {
            uint64_t d = ffma2(ax[k], q0.x, cc);
            d = ffma2(ay[k], q0.y, d);
            d = ffma2(az[k], q1.x, d);
            d = ffma2(aw[k], q1.y, d);
            float2 t = unpack2(d);
            mn[k] = fminf(mn[k], fminf(t.x, t.y));
        }
    }
    if (jn & 1) {   // never taken for these shapes, kept for safety
        const float* f = sp[(jn - 1) >> 1].f;
        const float bxx = f[0], byy = f[2], bzz = f[4], bww = f[6], c = f[8];
#pragma unroll
        for (int k = 0; k < T; k++) {
            float t = fmaf(unpack2(ax[k]).x, bxx, c);
            t = fmaf(unpack2(ay[k]).x, byy, t);
            t = fmaf(unpack2(az[k]).x, bzz, t);
            t = fmaf(unpack2(aw[k]).x, bww, t);
            mn[k] = fminf(mn[k], t);
        }
    }

    // ---- Epilogue: clamp >=0, invert, fire-and-forget REDG.MAX (relaxed) ----
#pragma unroll
    for (int k = 0; k < T; k++) {
        float v = fmaxf(mn[k] + a2[k], 0.0f);
        unsigned int key = 0x7FFFFFFFu - __float_as_uint(v);
        atomicMax(&g_minkey[base + k * THREADS], key);
    }
    __syncthreads();   // all threads' REDGs issued before the ticket

    // ---- Ticket: single acq_rel RMW replaces both __threadfence()s.
    // Release orders this CTA's REDGs before the inc; acquire covers the
    // last CTA's subsequent consume loads.
    if (tid == 0) {
        unsigned int old;
        asm volatile("atom.acq_rel.gpu.global.inc.u32 %0, [%1], %2;"
                     : "=r"(old)
                     : "l"(&g_tick), "r"((unsigned)(GRID_CTAS - 1))
                     : "memory");   // wraps to 0 -> replay-safe
        s_last = (old == GRID_CTAS - 1);
    }
    __syncthreads();
    if (!s_last) return;

    // ---- Last CTA: umin over 8192 keys (min key == max value), reset to 0 ----
    __shared__ unsigned int red[THREADS];
    unsigned int kmin = 0xFFFFFFFFu;
    const int nq = n / 4;     // 2048 uint4
#pragma unroll
    for (int q = tid; q < nq; q += THREADS) {   // 8 independent L2-direct loads
        const uint4* p4 = reinterpret_cast<const uint4*>(g_minkey) + q;
        uint4 s = __ldcg(p4);
        reinterpret_cast<uint4*>(g_minkey)[q] = make_uint4(0u, 0u, 0u, 0u);
        kmin = min(kmin, min(min(s.x, s.y), min(s.z, s.w)));
    }
    red[tid] = kmin;
    __syncthreads();
    for (int off = THREADS / 2; off >= 32; off >>= 1) {
        if (tid < off) red[tid] = min(red[tid], red[tid + off]);
        __syncthreads();
    }
    if (tid < 32) {
        unsigned int w = red[tid];
#pragma unroll
        for (int off = 16; off > 0; off >>= 1)
            w = min(w, __shfl_xor_sync(0xffffffffu, w, off));
        if (tid == 0)
            out[0] = __uint_as_float(0x7FFFFFFFu - w);   // LOSS_WEIGHT = 1.0
    }
}

extern "C" void kernel_launch(void* const* d_in, const int* in_sizes, int n_in,
                              void* d_out, int out_size) {
    const float* adv = (const float*)d_in[0];
    const float* ori = (const float*)d_in[1];
    float* out = (float*)d_out;

    const int n = in_sizes[0] / 4;   // 8192
    const int m = in_sizes[1] / 4;   // 8192

    dim3 grid((n + ADV_PER_BLOCK - 1) / ADV_PER_BLOCK, SPLITS);
    hd_fused<<<grid, THREADS>>>(adv, ori, out, n, m);
}